// round 2
// baseline (speedup 1.0000x reference)
#include <cuda_runtime.h>
#include <math.h>

// Problem dims
#define NR   512     // N rows (tokens)
#define DM   512     // d_model
#define NH   8       // heads
#define HE   64      // head dim
#define FF   2048    // ffn dim
#define NL   6       // layers
#define MIX3 768     // MIX*3

// ---------------- scratch (device globals; no allocation) ----------------
__device__ float g_h[NR * DM];
__device__ float g_q[NR * DM];
__device__ float g_k[NR * DM];
__device__ float g_v[NR * DM];
__device__ float g_attn[NR * DM];
__device__ float g_tmp[NR * DM];
__device__ float g_ffn[NR * FF];

// ---------------- embedding + positional concat ----------------
__global__ void embed_kernel(const int* __restrict__ x, const int* __restrict__ ip,
                             const float* __restrict__ emb, const float* __restrict__ pe) {
    int n = blockIdx.x;          // 512 blocks
    int d = threadIdx.x;         // 256 threads
    int tok = x[n];
    int i   = ip[0];
    g_h[n * DM + d]       = emb[tok * 256 + d];
    g_h[n * DM + 256 + d] = pe[i * 256 + d];
}

// ---------------- generic tiled GEMM: C = act(A @ B + bias) ----------------
// A: MxK row-major, B: KxN row-major, bias: N, C: MxN row-major.
// ACT: 0=none, 1=phi (elu+1), 2=relu
#define BM 64
#define BN 64
#define BK 16

template <int ACT>
__global__ __launch_bounds__(256) void gemm_kernel(
    const float* __restrict__ A, const float* __restrict__ B,
    const float* __restrict__ bias, float* __restrict__ C,
    int M, int N, int K)
{
    __shared__ float As[BK][BM + 1];   // padded: transposed store
    __shared__ float Bs[BK][BN];

    const int tid = threadIdx.x;
    const int tx = tid & 15;           // 0..15 (cols)
    const int ty = tid >> 4;           // 0..15 (rows)

    const int m0 = blockIdx.y * BM;
    const int n0 = blockIdx.x * BN;

    float acc[4][4];
#pragma unroll
    for (int i = 0; i < 4; i++)
#pragma unroll
        for (int j = 0; j < 4; j++) acc[i][j] = 0.f;

    // A-load mapping: kk = tid&15, r = tid>>4, 4 rows strided by 16
    // B-load mapping: nn = tid&63, kq = tid>>6, 4 k strided by 4
    const int a_k = tid & 15;
    const int a_r = tid >> 4;
    const int b_n = tid & 63;
    const int b_k = tid >> 6;

    for (int k0 = 0; k0 < K; k0 += BK) {
#pragma unroll
        for (int it = 0; it < 4; it++) {
            int row = a_r + 16 * it;
            As[a_k][row] = A[(size_t)(m0 + row) * K + (k0 + a_k)];
        }
#pragma unroll
        for (int it = 0; it < 4; it++) {
            int kk = b_k + 4 * it;
            Bs[kk][b_n] = B[(size_t)(k0 + kk) * N + (n0 + b_n)];
        }
        __syncthreads();

#pragma unroll
        for (int kk = 0; kk < BK; kk++) {
            float a[4], b[4];
#pragma unroll
            for (int i = 0; i < 4; i++) a[i] = As[kk][ty * 4 + i];
#pragma unroll
            for (int j = 0; j < 4; j++) b[j] = Bs[kk][tx * 4 + j];
#pragma unroll
            for (int i = 0; i < 4; i++)
#pragma unroll
                for (int j = 0; j < 4; j++)
                    acc[i][j] = fmaf(a[i], b[j], acc[i][j]);
        }
        __syncthreads();
    }

#pragma unroll
    for (int i = 0; i < 4; i++) {
        int row = m0 + ty * 4 + i;
#pragma unroll
        for (int j = 0; j < 4; j++) {
            int col = n0 + tx * 4 + j;
            float v = acc[i][j] + bias[col];
            if (ACT == 1) v = (v > 0.f) ? (v + 1.f) : __expf(v);
            if (ACT == 2) v = fmaxf(v, 0.f);
            C[(size_t)row * N + col] = v;
        }
    }
}

// ---------------- linear-attention state update + readout ----------------
// One block per (n, h); 64 threads (thread = output dim m).
// S = Si + K outer V ; Z = Zi + K ; den = Q.Z + eps ; attn = (Q @ S)/den
__global__ void attn_kernel(const float* __restrict__ Q, const float* __restrict__ Kmat,
                            const float* __restrict__ V,
                            const float* __restrict__ Si, const float* __restrict__ Zi,
                            float* __restrict__ S_out, float* __restrict__ Z_out,
                            float* __restrict__ attn)
{
    const int n = blockIdx.x;
    const int h = blockIdx.y;
    const int m = threadIdx.x;   // 0..63

    __shared__ float qs[HE], ks[HE], red[HE];

    const int baseqk = n * DM + h * HE;
    qs[m] = Q[baseqk + m];
    ks[m] = Kmat[baseqk + m];
    const float vm = V[baseqk + m];

    const size_t zbase = ((size_t)n * NH + h) * HE;
    const float z = Zi[zbase + m] + ks[m];
    Z_out[zbase + m] = z;

    red[m] = qs[m] * z;
    __syncthreads();
#pragma unroll
    for (int s = 32; s > 0; s >>= 1) {
        if (m < s) red[m] += red[m + s];
        __syncthreads();
    }
    const float den = red[0] + 1e-6f;

    const size_t sbase = ((size_t)n * NH + h) * HE * HE;
    float num = 0.f;
#pragma unroll 8
    for (int e = 0; e < HE; e++) {
        float s = Si[sbase + (size_t)e * HE + m] + ks[e] * vm;
        S_out[sbase + (size_t)e * HE + m] = s;
        num = fmaf(qs[e], s, num);
    }
    attn[baseqk + m] = num / den;
}

// ---------------- residual add + LayerNorm (in-place on hbuf) ----------------
// y may be null (plain LN). One block per row, 256 threads (2 elems each).
__global__ void add_ln_kernel(float* __restrict__ hbuf, const float* __restrict__ y,
                              const float* __restrict__ g, const float* __restrict__ b)
{
    const int n = blockIdx.x;
    const int t = threadIdx.x;     // 0..255
    __shared__ float red[256];
    __shared__ float s_mean, s_rstd;

    float v0 = hbuf[n * DM + t];
    float v1 = hbuf[n * DM + 256 + t];
    if (y) {
        v0 += y[n * DM + t];
        v1 += y[n * DM + 256 + t];
    }

    red[t] = v0 + v1;
    __syncthreads();
#pragma unroll
    for (int s = 128; s > 0; s >>= 1) {
        if (t < s) red[t] += red[t + s];
        __syncthreads();
    }
    if (t == 0) s_mean = red[0] * (1.f / DM);
    __syncthreads();
    const float mean = s_mean;

    float d0 = v0 - mean, d1 = v1 - mean;
    red[t] = d0 * d0 + d1 * d1;
    __syncthreads();
#pragma unroll
    for (int s = 128; s > 0; s >>= 1) {
        if (t < s) red[t] += red[t + s];
        __syncthreads();
    }
    if (t == 0) s_rstd = rsqrtf(red[0] * (1.f / DM) + 1e-5f);
    __syncthreads();
    const float rstd = s_rstd;

    hbuf[n * DM + t]       = d0 * rstd * g[t]       + b[t];
    hbuf[n * DM + 256 + t] = d1 * rstd * g[256 + t] + b[256 + t];
}

// ---------------- host-side launch ----------------
extern "C" void kernel_launch(void* const* d_in, const int* in_sizes, int n_in,
                              void* d_out, int out_size)
{
    const int*   x      = (const int*)  d_in[0];
    const int*   ip     = (const int*)  d_in[1];
    const float* emb    = (const float*)d_in[2];
    const float* pe     = (const float*)d_in[3];
    const float* Wq     = (const float*)d_in[4];
    const float* bq     = (const float*)d_in[5];
    const float* Wk     = (const float*)d_in[6];
    const float* bk     = (const float*)d_in[7];
    const float* Wv     = (const float*)d_in[8];
    const float* bv     = (const float*)d_in[9];
    const float* Wo     = (const float*)d_in[10];
    const float* bo     = (const float*)d_in[11];
    const float* ln1_g  = (const float*)d_in[12];
    const float* ln1_b  = (const float*)d_in[13];
    const float* lin1_w = (const float*)d_in[14];
    const float* lin1_b = (const float*)d_in[15];
    const float* lin2_w = (const float*)d_in[16];
    const float* lin2_b = (const float*)d_in[17];
    const float* ln2_g  = (const float*)d_in[18];
    const float* ln2_b  = (const float*)d_in[19];
    const float* lnf_g  = (const float*)d_in[20];
    const float* lnf_b  = (const float*)d_in[21];
    const float* pred_w = (const float*)d_in[22];
    const float* pred_b = (const float*)d_in[23];
    const float* Si     = (const float*)d_in[24];
    const float* Zi     = (const float*)d_in[25];

    float* out = (float*)d_out;
    // output layout: [y_hat (512*768) | Si (6*512*8*64*64) | Zi (6*512*8*64)]
    float* out_yhat = out;
    float* out_S    = out + (size_t)NR * MIX3;
    float* out_Z    = out_S + (size_t)NL * NR * NH * HE * HE;

    float *h, *q, *k, *v, *attn, *tmp, *ffn;
    cudaGetSymbolAddress((void**)&h,    g_h);
    cudaGetSymbolAddress((void**)&q,    g_q);
    cudaGetSymbolAddress((void**)&k,    g_k);
    cudaGetSymbolAddress((void**)&v,    g_v);
    cudaGetSymbolAddress((void**)&attn, g_attn);
    cudaGetSymbolAddress((void**)&tmp,  g_tmp);
    cudaGetSymbolAddress((void**)&ffn,  g_ffn);

    embed_kernel<<<NR, 256>>>(x, ip, emb, pe);

    const dim3 gDD(DM / BN, NR / BM);      // 8 x 8
    const dim3 gDF(FF / BN, NR / BM);      // 32 x 8
    const dim3 gFD(DM / BN, NR / BM);      // 8 x 8
    const dim3 gPred(MIX3 / BN, NR / BM);  // 12 x 8
    const dim3 gAttn(NR, NH);

    const size_t wsz = (size_t)DM * DM;
    const size_t ssz = (size_t)NR * NH * HE * HE;
    const size_t zsz = (size_t)NR * NH * HE;

    for (int l = 0; l < NL; l++) {
        gemm_kernel<1><<<gDD, 256>>>(h, Wq + l * wsz, bq + l * DM, q, NR, DM, DM);
        gemm_kernel<1><<<gDD, 256>>>(h, Wk + l * wsz, bk + l * DM, k, NR, DM, DM);
        gemm_kernel<0><<<gDD, 256>>>(h, Wv + l * wsz, bv + l * DM, v, NR, DM, DM);

        attn_kernel<<<gAttn, HE>>>(q, k, v, Si + l * ssz, Zi + l * zsz,
                                   out_S + l * ssz, out_Z + l * zsz, attn);

        gemm_kernel<0><<<gDD, 256>>>(attn, Wo + l * wsz, bo + l * DM, tmp, NR, DM, DM);
        add_ln_kernel<<<NR, 256>>>(h, tmp, ln1_g + l * DM, ln1_b + l * DM);

        gemm_kernel<2><<<gDF, 256>>>(h, lin1_w + (size_t)l * DM * FF, lin1_b + l * FF,
                                     ffn, NR, FF, DM);
        gemm_kernel<0><<<gFD, 256>>>(ffn, lin2_w + (size_t)l * FF * DM, lin2_b + l * DM,
                                     tmp, NR, DM, FF);
        add_ln_kernel<<<NR, 256>>>(h, tmp, ln2_g + l * DM, ln2_b + l * DM);
    }

    add_ln_kernel<<<NR, 256>>>(h, (const float*)nullptr, lnf_g, lnf_b);
    gemm_kernel<0><<<gPred, 256>>>(h, pred_w, pred_b, out_yhat, NR, MIX3, DM);
}

// round 3
// speedup vs baseline: 2.4355x; 2.4355x over previous
#include <cuda_runtime.h>
#include <math.h>

// Problem dims
#define NR   512     // N rows (tokens)
#define DM   512     // d_model
#define NH   8       // heads
#define HE   64      // head dim
#define FF   2048    // ffn dim
#define NL   6       // layers
#define MIX3 768     // MIX*3

// ---------------- scratch (device globals; no allocation) ----------------
__device__ float g_h[NR * DM];
__device__ float g_q[NR * DM];
__device__ float g_k[NR * DM];
__device__ float g_v[NR * DM];
__device__ float g_attn[NR * DM];
__device__ float g_ffn[NR * FF];
__device__ float g_part[4 * NR * DM];   // split-K partials (max 4 splits)

// ---------------- embedding + positional concat ----------------
__global__ void embed_kernel(const int* __restrict__ x, const int* __restrict__ ip,
                             const float* __restrict__ emb, const float* __restrict__ pe) {
    int n = blockIdx.x;          // 512 blocks
    int d = threadIdx.x;         // 256 threads
    int tok = x[n];
    int i   = ip[0];
    g_h[n * DM + d]       = emb[tok * 256 + d];
    g_h[n * DM + 256 + d] = pe[i * 256 + d];
}

// ---------------- GEMM core: 64x64 tile, BK=16, double-buffered ----------------
// C[64x64 tile] = act(A[m0:m0+64, kStart:kEnd] @ B[kStart:kEnd, n0:n0+64] + bias)
// ACT: 0=none, 1=phi (elu+1), 2=relu. bias may be null.
template <int ACT>
__device__ __forceinline__ void gemm_body(
    const float* __restrict__ A, const float* __restrict__ B,
    const float* __restrict__ bias, float* __restrict__ C,
    int N, int K, int kStart, int kEnd, int m0, int n0)
{
    __shared__ float As[2][16][68];   // transposed, stride 68 (16B-aligned rows)
    __shared__ float Bs[2][16][64];

    const int t   = threadIdx.x;
    const int ar  = t >> 2;           // 0..63  A row within tile
    const int ak4 = (t & 3) * 4;      // 0,4,8,12  A k-quad
    const int bk  = t >> 4;           // 0..15  B k row
    const int bn4 = (t & 15) * 4;     // B n-quad
    const int tx  = t & 15;           // micro col group
    const int ty  = t >> 4;           // micro row group

    float acc[4][4] = {};
    const int nt = (kEnd - kStart) >> 4;

    const float* Aptr = A + (size_t)(m0 + ar) * K + kStart + ak4;
    const float* Bptr = B + (size_t)(kStart + bk) * N + n0 + bn4;

    float4 aR = *(const float4*)Aptr;
    float4 bR = *(const float4*)Bptr;
    As[0][ak4 + 0][ar] = aR.x; As[0][ak4 + 1][ar] = aR.y;
    As[0][ak4 + 2][ar] = aR.z; As[0][ak4 + 3][ar] = aR.w;
    *(float4*)&Bs[0][bk][bn4] = bR;
    __syncthreads();

    for (int kt = 0; kt < nt; kt++) {
        const int cur = kt & 1;
        if (kt + 1 < nt) {
            aR = *(const float4*)(Aptr + (kt + 1) * 16);
            bR = *(const float4*)(Bptr + (size_t)(kt + 1) * 16 * N);
        }
#pragma unroll
        for (int kk = 0; kk < 16; kk++) {
            float4 a4 = *(const float4*)&As[cur][kk][ty * 4];
            float4 b4 = *(const float4*)&Bs[cur][kk][tx * 4];
            const float av[4] = {a4.x, a4.y, a4.z, a4.w};
            const float bv[4] = {b4.x, b4.y, b4.z, b4.w};
#pragma unroll
            for (int i = 0; i < 4; i++)
#pragma unroll
                for (int j = 0; j < 4; j++)
                    acc[i][j] = fmaf(av[i], bv[j], acc[i][j]);
        }
        if (kt + 1 < nt) {
            const int nx = cur ^ 1;
            As[nx][ak4 + 0][ar] = aR.x; As[nx][ak4 + 1][ar] = aR.y;
            As[nx][ak4 + 2][ar] = aR.z; As[nx][ak4 + 3][ar] = aR.w;
            *(float4*)&Bs[nx][bk][bn4] = bR;
        }
        __syncthreads();
    }

#pragma unroll
    for (int i = 0; i < 4; i++) {
        const int row = m0 + ty * 4 + i;
        float4 o;
        float* op = &o.x;
#pragma unroll
        for (int j = 0; j < 4; j++) {
            float v = acc[i][j];
            if (bias) v += bias[n0 + tx * 4 + j];
            if (ACT == 1) v = (v > 0.f) ? (v + 1.f) : __expf(v);
            if (ACT == 2) v = fmaxf(v, 0.f);
            op[j] = v;
        }
        *(float4*)&C[(size_t)row * N + n0 + tx * 4] = o;
    }
}

// Plain GEMM (full K), M = NR implicit via grid
template <int ACT>
__global__ __launch_bounds__(256) void gemm_kernel(
    const float* __restrict__ A, const float* __restrict__ B,
    const float* __restrict__ bias, float* __restrict__ C, int N, int K)
{
    gemm_body<ACT>(A, B, bias, C, N, K, 0, K, blockIdx.y * 64, blockIdx.x * 64);
}

// Split-K GEMM: blockIdx.z picks a K chunk; partials written to Cp + z*NR*N
__global__ __launch_bounds__(256) void gemm_splitk_kernel(
    const float* __restrict__ A, const float* __restrict__ B,
    float* __restrict__ Cp, int N, int K, int S)
{
    const int chunk = K / S;
    const int z = blockIdx.z;
    gemm_body<0>(A, B, nullptr, Cp + (size_t)z * NR * N,
                 N, K, z * chunk, (z + 1) * chunk, blockIdx.y * 64, blockIdx.x * 64);
}

// Fused QKV: blockIdx.z = 0(Q,phi) 1(K,phi) 2(V,none); grid (8,8,3)
__global__ __launch_bounds__(256) void gemm_qkv_kernel(
    const float* __restrict__ h,
    const float* __restrict__ Wq, const float* __restrict__ Wk, const float* __restrict__ Wv,
    const float* __restrict__ bq, const float* __restrict__ bk, const float* __restrict__ bv,
    float* __restrict__ q, float* __restrict__ k, float* __restrict__ v, int l)
{
    const size_t w = (size_t)l * DM * DM;
    const int m0 = blockIdx.y * 64, n0 = blockIdx.x * 64;
    if (blockIdx.z == 0)
        gemm_body<1>(h, Wq + w, bq + l * DM, q, DM, DM, 0, DM, m0, n0);
    else if (blockIdx.z == 1)
        gemm_body<1>(h, Wk + w, bk + l * DM, k, DM, DM, 0, DM, m0, n0);
    else
        gemm_body<0>(h, Wv + w, bv + l * DM, v, DM, DM, 0, DM, m0, n0);
}

// ---------------- linear-attention state update + readout ----------------
__global__ void attn_kernel(const float* __restrict__ Q, const float* __restrict__ Kmat,
                            const float* __restrict__ V,
                            const float* __restrict__ Si, const float* __restrict__ Zi,
                            float* __restrict__ S_out, float* __restrict__ Z_out,
                            float* __restrict__ attn)
{
    const int n = blockIdx.x;
    const int h = blockIdx.y;
    const int m = threadIdx.x;   // 0..63

    __shared__ float qs[HE], ks[HE], red[HE];

    const int baseqk = n * DM + h * HE;
    qs[m] = Q[baseqk + m];
    ks[m] = Kmat[baseqk + m];
    const float vm = V[baseqk + m];

    const size_t zbase = ((size_t)n * NH + h) * HE;
    const float z = Zi[zbase + m] + ks[m];
    Z_out[zbase + m] = z;

    red[m] = qs[m] * z;
    __syncthreads();
#pragma unroll
    for (int s = 32; s > 0; s >>= 1) {
        if (m < s) red[m] += red[m + s];
        __syncthreads();
    }
    const float den = red[0] + 1e-6f;

    const size_t sbase = ((size_t)n * NH + h) * HE * HE;
    float num = 0.f;
#pragma unroll 8
    for (int e = 0; e < HE; e++) {
        float s = Si[sbase + (size_t)e * HE + m] + ks[e] * vm;
        S_out[sbase + (size_t)e * HE + m] = s;
        num = fmaf(qs[e], s, num);
    }
    attn[baseqk + m] = num / den;
}

// ---------------- residual + split-K reduce + bias + LayerNorm (in-place) ----
// hbuf = LN(hbuf + sum_{p<P} part[p] + bias) * g + b   (part/bias may be null)
__global__ void add_ln_kernel(float* __restrict__ hbuf, const float* __restrict__ part,
                              int P, const float* __restrict__ bias,
                              const float* __restrict__ g, const float* __restrict__ b)
{
    const int n = blockIdx.x;
    const int t = threadIdx.x;     // 0..255
    __shared__ float red[256];
    __shared__ float s_mean, s_rstd;

    float v0 = hbuf[n * DM + t];
    float v1 = hbuf[n * DM + 256 + t];
    for (int p = 0; p < P; p++) {
        v0 += part[(size_t)p * NR * DM + n * DM + t];
        v1 += part[(size_t)p * NR * DM + n * DM + 256 + t];
    }
    if (bias) { v0 += bias[t]; v1 += bias[256 + t]; }

    red[t] = v0 + v1;
    __syncthreads();
#pragma unroll
    for (int s = 128; s > 0; s >>= 1) {
        if (t < s) red[t] += red[t + s];
        __syncthreads();
    }
    if (t == 0) s_mean = red[0] * (1.f / DM);
    __syncthreads();
    const float mean = s_mean;

    float d0 = v0 - mean, d1 = v1 - mean;
    red[t] = d0 * d0 + d1 * d1;
    __syncthreads();
#pragma unroll
    for (int s = 128; s > 0; s >>= 1) {
        if (t < s) red[t] += red[t + s];
        __syncthreads();
    }
    if (t == 0) s_rstd = rsqrtf(red[0] * (1.f / DM) + 1e-5f);
    __syncthreads();
    const float rstd = s_rstd;

    hbuf[n * DM + t]       = d0 * rstd * g[t]       + b[t];
    hbuf[n * DM + 256 + t] = d1 * rstd * g[256 + t] + b[256 + t];
}

// ---------------- host-side launch ----------------
extern "C" void kernel_launch(void* const* d_in, const int* in_sizes, int n_in,
                              void* d_out, int out_size)
{
    const int*   x      = (const int*)  d_in[0];
    const int*   ip     = (const int*)  d_in[1];
    const float* emb    = (const float*)d_in[2];
    const float* pe     = (const float*)d_in[3];
    const float* Wq     = (const float*)d_in[4];
    const float* bq     = (const float*)d_in[5];
    const float* Wk     = (const float*)d_in[6];
    const float* bk     = (const float*)d_in[7];
    const float* Wv     = (const float*)d_in[8];
    const float* bv     = (const float*)d_in[9];
    const float* Wo     = (const float*)d_in[10];
    const float* bo     = (const float*)d_in[11];
    const float* ln1_g  = (const float*)d_in[12];
    const float* ln1_b  = (const float*)d_in[13];
    const float* lin1_w = (const float*)d_in[14];
    const float* lin1_b = (const float*)d_in[15];
    const float* lin2_w = (const float*)d_in[16];
    const float* lin2_b = (const float*)d_in[17];
    const float* ln2_g  = (const float*)d_in[18];
    const float* ln2_b  = (const float*)d_in[19];
    const float* lnf_g  = (const float*)d_in[20];
    const float* lnf_b  = (const float*)d_in[21];
    const float* pred_w = (const float*)d_in[22];
    const float* pred_b = (const float*)d_in[23];
    const float* Si     = (const float*)d_in[24];
    const float* Zi     = (const float*)d_in[25];

    float* out = (float*)d_out;
    // output layout: [y_hat (512*768) | Si (6*512*8*64*64) | Zi (6*512*8*64)]
    float* out_yhat = out;
    float* out_S    = out + (size_t)NR * MIX3;
    float* out_Z    = out_S + (size_t)NL * NR * NH * HE * HE;

    float *h, *q, *k, *v, *attn, *ffn, *part;
    cudaGetSymbolAddress((void**)&h,    g_h);
    cudaGetSymbolAddress((void**)&q,    g_q);
    cudaGetSymbolAddress((void**)&k,    g_k);
    cudaGetSymbolAddress((void**)&v,    g_v);
    cudaGetSymbolAddress((void**)&attn, g_attn);
    cudaGetSymbolAddress((void**)&ffn,  g_ffn);
    cudaGetSymbolAddress((void**)&part, g_part);

    embed_kernel<<<NR, 256>>>(x, ip, emb, pe);

    const dim3 gQKV(DM / 64, NR / 64, 3);     // 8x8x3 = 192 blocks
    const dim3 gWo(DM / 64, NR / 64, 2);      // split-K 2 -> 128 blocks
    const dim3 gF1(FF / 64, NR / 64);         // 32x8 = 256 blocks
    const dim3 gF2(DM / 64, NR / 64, 4);      // split-K 4 -> 256 blocks
    const dim3 gPred(MIX3 / 64, NR / 64);     // 12x8 = 96 blocks
    const dim3 gAttn(NR, NH);

    const size_t ssz = (size_t)NR * NH * HE * HE;
    const size_t zsz = (size_t)NR * NH * HE;

    for (int l = 0; l < NL; l++) {
        gemm_qkv_kernel<<<gQKV, 256>>>(h, Wq, Wk, Wv, bq, bk, bv, q, k, v, l);

        attn_kernel<<<gAttn, HE>>>(q, k, v, Si + l * ssz, Zi + l * zsz,
                                   out_S + l * ssz, out_Z + l * zsz, attn);

        gemm_splitk_kernel<<<gWo, 256>>>(attn, Wo + (size_t)l * DM * DM, part, DM, DM, 2);
        add_ln_kernel<<<NR, 256>>>(h, part, 2, bo + l * DM, ln1_g + l * DM, ln1_b + l * DM);

        gemm_kernel<2><<<gF1, 256>>>(h, lin1_w + (size_t)l * DM * FF, lin1_b + l * FF,
                                     ffn, FF, DM);
        gemm_splitk_kernel<<<gF2, 256>>>(ffn, lin2_w + (size_t)l * FF * DM, part, DM, FF, 4);
        add_ln_kernel<<<NR, 256>>>(h, part, 4, lin2_b + l * DM, ln2_g + l * DM, ln2_b + l * DM);
    }

    add_ln_kernel<<<NR, 256>>>(h, (const float*)nullptr, 0, (const float*)nullptr, lnf_g, lnf_b);
    gemm_kernel<0><<<gPred, 256>>>(h, pred_w, pred_b, out_yhat, MIX3, DM);
}

// round 4
// speedup vs baseline: 2.7890x; 1.1451x over previous
#include <cuda_runtime.h>
#include <math.h>

// Problem dims
#define NR   512     // N rows (tokens)
#define DM   512     // d_model
#define NH   8       // heads
#define HE   64      // head dim
#define FF   2048    // ffn dim
#define NL   6       // layers
#define MIX3 768     // MIX*3

// ---------------- scratch (device globals; no allocation) ----------------
__device__ float g_h[NR * DM];
__device__ float g_q[NR * DM];
__device__ float g_k[NR * DM];
__device__ float g_v[NR * DM];
__device__ float g_attn[NR * DM];
__device__ float g_ffn[NR * FF];
__device__ float g_part[4 * NR * DM];   // split-K partials (max 4 splits)

// ---------------- embedding + positional concat ----------------
__global__ void embed_kernel(const int* __restrict__ x, const int* __restrict__ ip,
                             const float* __restrict__ emb, const float* __restrict__ pe) {
    int n = blockIdx.x;          // 512 blocks
    int d = threadIdx.x;         // 256 threads
    int tok = x[n];
    int i   = ip[0];
    g_h[n * DM + d]       = emb[tok * 256 + d];
    g_h[n * DM + 256 + d] = pe[i * 256 + d];
}

// ---------------- TF32 tensor-core GEMM core ----------------
// C[64x64 tile] = act(A[m0:.., kStart:kEnd] @ B[kStart:kEnd, n0:..] + bias)
// A row-major MxK, B row-major KxN. 256 threads = 8 warps (2m x 4n),
// warp tile 32x16 via mma.m16n8k8 (2 m-frags x 2 n-frags).
// ACT: 0=none, 1=phi (elu+1), 2=relu. bias may be null.

__device__ __forceinline__ unsigned f2tf32(float f) {
    unsigned u;
    asm("cvt.rna.tf32.f32 %0, %1;" : "=r"(u) : "f"(f));
    return u;
}

template <int ACT>
__device__ __forceinline__ void gemm_body(
    const float* __restrict__ A, const float* __restrict__ B,
    const float* __restrict__ bias, float* __restrict__ C,
    int N, int K, int kStart, int kEnd, int m0, int n0)
{
    // As: 64 rows x 16 k (padded to 20); Bs transposed: 64 n x 16 k (padded 20)
    __shared__ unsigned As[2][64][20];
    __shared__ unsigned Bs[2][64][20];

    const int t    = threadIdx.x;
    const int warp = t >> 5;
    const int lane = t & 31;
    const int g    = lane >> 2;       // 0..7
    const int tg   = lane & 3;        // 0..3
    const int wm   = warp >> 2;       // 0..1 -> m offset 32*wm
    const int wn   = warp & 3;        // 0..3 -> n offset 16*wn

    // global load mapping
    const int a_r  = t >> 2;          // 0..63 A row
    const int a_k4 = (t & 3) * 4;     // 0,4,8,12
    const int b_k  = t >> 4;          // 0..15 B k-row
    const int b_n4 = (t & 15) * 4;    // n quad

    const int nt = (kEnd - kStart) >> 4;

    const float* Aptr = A + (size_t)(m0 + a_r) * K + kStart + a_k4;
    const float* Bptr = B + (size_t)(kStart + b_k) * N + n0 + b_n4;

    float c[2][2][4];
#pragma unroll
    for (int i = 0; i < 2; i++)
#pragma unroll
        for (int j = 0; j < 2; j++)
#pragma unroll
            for (int r = 0; r < 4; r++) c[i][j][r] = 0.f;

    float4 aG = *(const float4*)Aptr;
    float4 bG = *(const float4*)Bptr;
    {
        As[0][a_r][a_k4 + 0] = f2tf32(aG.x); As[0][a_r][a_k4 + 1] = f2tf32(aG.y);
        As[0][a_r][a_k4 + 2] = f2tf32(aG.z); As[0][a_r][a_k4 + 3] = f2tf32(aG.w);
        Bs[0][b_n4 + 0][b_k] = f2tf32(bG.x); Bs[0][b_n4 + 1][b_k] = f2tf32(bG.y);
        Bs[0][b_n4 + 2][b_k] = f2tf32(bG.z); Bs[0][b_n4 + 3][b_k] = f2tf32(bG.w);
    }
    __syncthreads();

    for (int kt = 0; kt < nt; kt++) {
        const int cur = kt & 1;
        if (kt + 1 < nt) {
            aG = *(const float4*)(Aptr + (kt + 1) * 16);
            bG = *(const float4*)(Bptr + (size_t)(kt + 1) * 16 * N);
        }

#pragma unroll
        for (int ks = 0; ks < 2; ks++) {         // two k=8 steps
            const int kk = ks * 8;
            unsigned a[2][4], b[2][2];
#pragma unroll
            for (int mt = 0; mt < 2; mt++) {
                const int row = wm * 32 + mt * 16;
                a[mt][0] = As[cur][row + g][kk + tg];
                a[mt][1] = As[cur][row + g + 8][kk + tg];
                a[mt][2] = As[cur][row + g][kk + tg + 4];
                a[mt][3] = As[cur][row + g + 8][kk + tg + 4];
            }
#pragma unroll
            for (int ntl = 0; ntl < 2; ntl++) {
                const int col = wn * 16 + ntl * 8 + g;
                b[ntl][0] = Bs[cur][col][kk + tg];
                b[ntl][1] = Bs[cur][col][kk + tg + 4];
            }
#pragma unroll
            for (int mt = 0; mt < 2; mt++)
#pragma unroll
                for (int ntl = 0; ntl < 2; ntl++) {
                    asm volatile(
                        "mma.sync.aligned.m16n8k8.row.col.f32.tf32.tf32.f32 "
                        "{%0,%1,%2,%3}, {%4,%5,%6,%7}, {%8,%9}, {%0,%1,%2,%3};"
                        : "+f"(c[mt][ntl][0]), "+f"(c[mt][ntl][1]),
                          "+f"(c[mt][ntl][2]), "+f"(c[mt][ntl][3])
                        : "r"(a[mt][0]), "r"(a[mt][1]), "r"(a[mt][2]), "r"(a[mt][3]),
                          "r"(b[ntl][0]), "r"(b[ntl][1]));
                }
        }

        if (kt + 1 < nt) {
            const int nx = cur ^ 1;
            As[nx][a_r][a_k4 + 0] = f2tf32(aG.x); As[nx][a_r][a_k4 + 1] = f2tf32(aG.y);
            As[nx][a_r][a_k4 + 2] = f2tf32(aG.z); As[nx][a_r][a_k4 + 3] = f2tf32(aG.w);
            Bs[nx][b_n4 + 0][b_k] = f2tf32(bG.x); Bs[nx][b_n4 + 1][b_k] = f2tf32(bG.y);
            Bs[nx][b_n4 + 2][b_k] = f2tf32(bG.z); Bs[nx][b_n4 + 3][b_k] = f2tf32(bG.w);
        }
        __syncthreads();
    }

    // epilogue: c[mt][nt] regs -> C, rows g/g+8, cols tg*2, tg*2+1
#pragma unroll
    for (int mt = 0; mt < 2; mt++) {
#pragma unroll
        for (int ntl = 0; ntl < 2; ntl++) {
#pragma unroll
            for (int half = 0; half < 2; half++) {
                const int row = m0 + wm * 32 + mt * 16 + g + half * 8;
                const int col = n0 + wn * 16 + ntl * 8 + tg * 2;
                float v0 = c[mt][ntl][half * 2 + 0];
                float v1 = c[mt][ntl][half * 2 + 1];
                if (bias) { v0 += bias[col]; v1 += bias[col + 1]; }
                if (ACT == 1) {
                    v0 = (v0 > 0.f) ? (v0 + 1.f) : __expf(v0);
                    v1 = (v1 > 0.f) ? (v1 + 1.f) : __expf(v1);
                }
                if (ACT == 2) { v0 = fmaxf(v0, 0.f); v1 = fmaxf(v1, 0.f); }
                float2 o = make_float2(v0, v1);
                *(float2*)&C[(size_t)row * N + col] = o;
            }
        }
    }
}

// Plain GEMM (full K)
template <int ACT>
__global__ __launch_bounds__(256, 2) void gemm_kernel(
    const float* __restrict__ A, const float* __restrict__ B,
    const float* __restrict__ bias, float* __restrict__ C, int N, int K)
{
    gemm_body<ACT>(A, B, bias, C, N, K, 0, K, blockIdx.y * 64, blockIdx.x * 64);
}

// Split-K GEMM: blockIdx.z picks a K chunk; partials to Cp + z*NR*N
__global__ __launch_bounds__(256, 2) void gemm_splitk_kernel(
    const float* __restrict__ A, const float* __restrict__ B,
    float* __restrict__ Cp, int N, int K, int S)
{
    const int chunk = K / S;
    const int z = blockIdx.z;
    gemm_body<0>(A, B, nullptr, Cp + (size_t)z * NR * N,
                 N, K, z * chunk, (z + 1) * chunk, blockIdx.y * 64, blockIdx.x * 64);
}

// Fused QKV: blockIdx.z = 0(Q,phi) 1(K,phi) 2(V,none); grid (8,8,3)
__global__ __launch_bounds__(256, 2) void gemm_qkv_kernel(
    const float* __restrict__ h,
    const float* __restrict__ Wq, const float* __restrict__ Wk, const float* __restrict__ Wv,
    const float* __restrict__ bq, const float* __restrict__ bk, const float* __restrict__ bv,
    float* __restrict__ q, float* __restrict__ k, float* __restrict__ v, int l)
{
    const size_t w = (size_t)l * DM * DM;
    const int m0 = blockIdx.y * 64, n0 = blockIdx.x * 64;
    if (blockIdx.z == 0)
        gemm_body<1>(h, Wq + w, bq + l * DM, q, DM, DM, 0, DM, m0, n0);
    else if (blockIdx.z == 1)
        gemm_body<1>(h, Wk + w, bk + l * DM, k, DM, DM, 0, DM, m0, n0);
    else
        gemm_body<0>(h, Wv + w, bv + l * DM, v, DM, DM, 0, DM, m0, n0);
}

// ---------------- linear-attention state update + readout ----------------
__global__ void attn_kernel(const float* __restrict__ Q, const float* __restrict__ Kmat,
                            const float* __restrict__ V,
                            const float* __restrict__ Si, const float* __restrict__ Zi,
                            float* __restrict__ S_out, float* __restrict__ Z_out,
                            float* __restrict__ attn)
{
    const int n = blockIdx.x;
    const int h = blockIdx.y;
    const int m = threadIdx.x;   // 0..63

    __shared__ float qs[HE], ks[HE], red[HE];

    const int baseqk = n * DM + h * HE;
    qs[m] = Q[baseqk + m];
    ks[m] = Kmat[baseqk + m];
    const float vm = V[baseqk + m];

    const size_t zbase = ((size_t)n * NH + h) * HE;
    const float z = Zi[zbase + m] + ks[m];
    Z_out[zbase + m] = z;

    red[m] = qs[m] * z;
    __syncthreads();
#pragma unroll
    for (int s = 32; s > 0; s >>= 1) {
        if (m < s) red[m] += red[m + s];
        __syncthreads();
    }
    const float den = red[0] + 1e-6f;

    const size_t sbase = ((size_t)n * NH + h) * HE * HE;
    float num = 0.f;
#pragma unroll 8
    for (int e = 0; e < HE; e++) {
        float s = Si[sbase + (size_t)e * HE + m] + ks[e] * vm;
        S_out[sbase + (size_t)e * HE + m] = s;
        num = fmaf(qs[e], s, num);
    }
    attn[baseqk + m] = num / den;
}

// ---------------- residual + split-K reduce + bias + LayerNorm (in-place) ----
__global__ void add_ln_kernel(float* __restrict__ hbuf, const float* __restrict__ part,
                              int P, const float* __restrict__ bias,
                              const float* __restrict__ g, const float* __restrict__ b)
{
    const int n = blockIdx.x;
    const int t = threadIdx.x;     // 0..255
    __shared__ float red[256];
    __shared__ float s_mean, s_rstd;

    float v0 = hbuf[n * DM + t];
    float v1 = hbuf[n * DM + 256 + t];
    for (int p = 0; p < P; p++) {
        v0 += part[(size_t)p * NR * DM + n * DM + t];
        v1 += part[(size_t)p * NR * DM + n * DM + 256 + t];
    }
    if (bias) { v0 += bias[t]; v1 += bias[256 + t]; }

    red[t] = v0 + v1;
    __syncthreads();
#pragma unroll
    for (int s = 128; s > 0; s >>= 1) {
        if (t < s) red[t] += red[t + s];
        __syncthreads();
    }
    if (t == 0) s_mean = red[0] * (1.f / DM);
    __syncthreads();
    const float mean = s_mean;

    float d0 = v0 - mean, d1 = v1 - mean;
    red[t] = d0 * d0 + d1 * d1;
    __syncthreads();
#pragma unroll
    for (int s = 128; s > 0; s >>= 1) {
        if (t < s) red[t] += red[t + s];
        __syncthreads();
    }
    if (t == 0) s_rstd = rsqrtf(red[0] * (1.f / DM) + 1e-5f);
    __syncthreads();
    const float rstd = s_rstd;

    hbuf[n * DM + t]       = d0 * rstd * g[t]       + b[t];
    hbuf[n * DM + 256 + t] = d1 * rstd * g[256 + t] + b[256 + t];
}

// ---------------- host-side launch ----------------
extern "C" void kernel_launch(void* const* d_in, const int* in_sizes, int n_in,
                              void* d_out, int out_size)
{
    const int*   x      = (const int*)  d_in[0];
    const int*   ip     = (const int*)  d_in[1];
    const float* emb    = (const float*)d_in[2];
    const float* pe     = (const float*)d_in[3];
    const float* Wq     = (const float*)d_in[4];
    const float* bq     = (const float*)d_in[5];
    const float* Wk     = (const float*)d_in[6];
    const float* bk     = (const float*)d_in[7];
    const float* Wv     = (const float*)d_in[8];
    const float* bv     = (const float*)d_in[9];
    const float* Wo     = (const float*)d_in[10];
    const float* bo     = (const float*)d_in[11];
    const float* ln1_g  = (const float*)d_in[12];
    const float* ln1_b  = (const float*)d_in[13];
    const float* lin1_w = (const float*)d_in[14];
    const float* lin1_b = (const float*)d_in[15];
    const float* lin2_w = (const float*)d_in[16];
    const float* lin2_b = (const float*)d_in[17];
    const float* ln2_g  = (const float*)d_in[18];
    const float* ln2_b  = (const float*)d_in[19];
    const float* lnf_g  = (const float*)d_in[20];
    const float* lnf_b  = (const float*)d_in[21];
    const float* pred_w = (const float*)d_in[22];
    const float* pred_b = (const float*)d_in[23];
    const float* Si     = (const float*)d_in[24];
    const float* Zi     = (const float*)d_in[25];

    float* out = (float*)d_out;
    float* out_yhat = out;
    float* out_S    = out + (size_t)NR * MIX3;
    float* out_Z    = out_S + (size_t)NL * NR * NH * HE * HE;

    float *h, *q, *k, *v, *attn, *ffn, *part;
    cudaGetSymbolAddress((void**)&h,    g_h);
    cudaGetSymbolAddress((void**)&q,    g_q);
    cudaGetSymbolAddress((void**)&k,    g_k);
    cudaGetSymbolAddress((void**)&v,    g_v);
    cudaGetSymbolAddress((void**)&attn, g_attn);
    cudaGetSymbolAddress((void**)&ffn,  g_ffn);
    cudaGetSymbolAddress((void**)&part, g_part);

    embed_kernel<<<NR, 256>>>(x, ip, emb, pe);

    const dim3 gQKV(DM / 64, NR / 64, 3);     // 192 blocks
    const dim3 gWo(DM / 64, NR / 64, 2);      // 128 blocks (split-K 2)
    const dim3 gF1(FF / 64, NR / 64);         // 256 blocks
    const dim3 gF2(DM / 64, NR / 64, 4);      // 256 blocks (split-K 4)
    const dim3 gPred(MIX3 / 64, NR / 64);     // 96 blocks
    const dim3 gAttn(NR, NH);

    const size_t ssz = (size_t)NR * NH * HE * HE;
    const size_t zsz = (size_t)NR * NH * HE;

    for (int l = 0; l < NL; l++) {
        gemm_qkv_kernel<<<gQKV, 256>>>(h, Wq, Wk, Wv, bq, bk, bv, q, k, v, l);

        attn_kernel<<<gAttn, HE>>>(q, k, v, Si + l * ssz, Zi + l * zsz,
                                   out_S + l * ssz, out_Z + l * zsz, attn);

        gemm_splitk_kernel<<<gWo, 256>>>(attn, Wo + (size_t)l * DM * DM, part, DM, DM, 2);
        add_ln_kernel<<<NR, 256>>>(h, part, 2, bo + l * DM, ln1_g + l * DM, ln1_b + l * DM);

        gemm_kernel<2><<<gF1, 256>>>(h, lin1_w + (size_t)l * DM * FF, lin1_b + l * FF,
                                     ffn, FF, DM);
        gemm_splitk_kernel<<<gF2, 256>>>(ffn, lin2_w + (size_t)l * FF * DM, part, DM, FF, 4);
        add_ln_kernel<<<NR, 256>>>(h, part, 4, lin2_b + l * DM, ln2_g + l * DM, ln2_b + l * DM);
    }

    add_ln_kernel<<<NR, 256>>>(h, (const float*)nullptr, 0, (const float*)nullptr, lnf_g, lnf_b);
    gemm_kernel<0><<<gPred, 256>>>(h, pred_w, pred_b, out_yhat, MIX3, DM);
}

// round 5
// speedup vs baseline: 3.2293x; 1.1579x over previous
#include <cuda_runtime.h>
#include <math.h>

// Problem dims
#define NR   512
#define DM   512
#define NH   8
#define HE   64
#define FF   2048
#define NL   6
#define MIX3 768

// ---------------- scratch (device globals; no allocation) ----------------
__device__ float g_h[NR * DM];
__device__ float g_q[NR * DM];
__device__ float g_k[NR * DM];
__device__ float g_v[NR * DM];
__device__ float g_attn[NR * DM];
__device__ float g_ffn[NR * FF];
__device__ float g_part[4 * NR * DM];

// ---------------- embedding + positional concat ----------------
__global__ void embed_kernel(const int* __restrict__ x, const int* __restrict__ ip,
                             const float* __restrict__ emb, const float* __restrict__ pe) {
    int n = blockIdx.x;
    int d = threadIdx.x;
    int tok = x[n];
    int i   = ip[0];
    g_h[n * DM + d]       = emb[tok * 256 + d];
    g_h[n * DM + 256 + d] = pe[i * 256 + d];
}

// ---------------- TF32 tensor-core GEMM core (fragment-major smem) --------
// Tile 64x64, BK=32, 256 threads = 8 warps (2m x 4n), warp tile 32x16.
// A smem: [step4][blk4][g8] * 20 words, vec4 slot = half + 2*khalf
// B smem: [step4][col64] * 10 words, vec2 slot = khalf, tg swizzled

__device__ __forceinline__ unsigned f2tf32(float f) {
    unsigned u;
    asm("cvt.rna.tf32.f32 %0, %1;" : "=r"(u) : "f"(f));
    return u;
}

__device__ __forceinline__ int bswz(int tg, int n) {
    return (tg + (n >> 2) + (n >> 4)) & 3;
}

template <int ACT>
__device__ __forceinline__ void gemm_body(
    const float* __restrict__ A, const float* __restrict__ B,
    const float* __restrict__ bias, float* __restrict__ C,
    int N, int K, int kStart, int kEnd, int m0, int n0)
{
    __shared__ __align__(16) unsigned As[2][2560];
    __shared__ __align__(16) unsigned Bs[2][2560];

    const int t    = threadIdx.x;
    const int warp = t >> 5;
    const int lane = t & 31;
    const int g    = lane >> 2;
    const int tg   = lane & 3;
    const int wm   = warp >> 2;       // 0..1
    const int wn   = warp & 3;        // 0..3

    // A loader: row ar, k quads ak4 and ak4+16
    const int ar    = t >> 2;         // 0..63
    const int ak4   = (t & 3) * 4;    // 0,4,8,12
    const int ablk  = ar >> 4;
    const int ag    = ar & 7;
    const int ahalf = (ar >> 3) & 1;
    // B loader: k rows bk and bk+16, n quad bn4
    const int bk  = t >> 4;           // 0..15
    const int bn4 = (t & 15) * 4;

    const float* Ap = A + (size_t)(m0 + ar) * K + kStart + ak4;
    const float* Bp = B + (size_t)(kStart + bk) * N + n0 + bn4;

    const int nt = (kEnd - kStart) >> 5;   // BK = 32

    float c[2][2][4];
#pragma unroll
    for (int i = 0; i < 2; i++)
#pragma unroll
        for (int j = 0; j < 2; j++)
#pragma unroll
            for (int r = 0; r < 4; r++) c[i][j][r] = 0.f;

    float4 aR0 = *(const float4*)Ap;
    float4 aR1 = *(const float4*)(Ap + 16);
    float4 bR0 = *(const float4*)Bp;
    float4 bR1 = *(const float4*)(Bp + (size_t)16 * N);

    // ---- store helpers (macros keep regs simple) ----
#define ST_A(buf, kkbase, v)                                                  \
    {                                                                         \
        const float va[4] = {(v).x, (v).y, (v).z, (v).w};                     \
        _Pragma("unroll")                                                     \
        for (int j = 0; j < 4; j++) {                                         \
            const int kq   = (kkbase) + j;                                    \
            const int step = kq >> 3;                                         \
            const int kh   = (kq >> 2) & 1;                                   \
            As[buf][((step * 4 + ablk) * 8 + ag) * 20 + j * 4 + ahalf + 2 * kh] \
                = f2tf32(va[j]);                                              \
        }                                                                     \
    }
#define ST_B(buf, kk, v)                                                      \
    {                                                                         \
        const float vb[4] = {(v).x, (v).y, (v).z, (v).w};                     \
        const int step = (kk) >> 3;                                           \
        const int tgk  = (kk) & 3;                                            \
        const int kh   = ((kk) >> 2) & 1;                                     \
        _Pragma("unroll")                                                     \
        for (int j = 0; j < 4; j++) {                                         \
            const int n = bn4 + j;                                            \
            Bs[buf][(step * 64 + n) * 10 + bswz(tgk, n) * 2 + kh] = f2tf32(vb[j]); \
        }                                                                     \
    }

    ST_A(0, ak4, aR0);
    ST_A(0, ak4 + 16, aR1);
    ST_B(0, bk, bR0);
    ST_B(0, bk + 16, bR1);
    __syncthreads();

    for (int kt = 0; kt < nt; kt++) {
        const int cur = kt & 1;
        if (kt + 1 < nt) {
            const float* Ap2 = Ap + (kt + 1) * 32;
            const float* Bp2 = Bp + (size_t)(kt + 1) * 32 * N;
            aR0 = *(const float4*)Ap2;
            aR1 = *(const float4*)(Ap2 + 16);
            bR0 = *(const float4*)Bp2;
            bR1 = *(const float4*)(Bp2 + (size_t)16 * N);
        }

#pragma unroll
        for (int step = 0; step < 4; step++) {
            uint4 af[2];
#pragma unroll
            for (int mt = 0; mt < 2; mt++)
                af[mt] = *(const uint4*)&As[cur][((step * 4 + wm * 2 + mt) * 8 + g) * 20 + tg * 4];
            uint2 bf[2];
#pragma unroll
            for (int ntl = 0; ntl < 2; ntl++) {
                const int col = wn * 16 + ntl * 8 + g;
                bf[ntl] = *(const uint2*)&Bs[cur][(step * 64 + col) * 10 + bswz(tg, col) * 2];
            }
#pragma unroll
            for (int mt = 0; mt < 2; mt++)
#pragma unroll
                for (int ntl = 0; ntl < 2; ntl++) {
                    asm volatile(
                        "mma.sync.aligned.m16n8k8.row.col.f32.tf32.tf32.f32 "
                        "{%0,%1,%2,%3}, {%4,%5,%6,%7}, {%8,%9}, {%0,%1,%2,%3};"
                        : "+f"(c[mt][ntl][0]), "+f"(c[mt][ntl][1]),
                          "+f"(c[mt][ntl][2]), "+f"(c[mt][ntl][3])
                        : "r"(af[mt].x), "r"(af[mt].y), "r"(af[mt].z), "r"(af[mt].w),
                          "r"(bf[ntl].x), "r"(bf[ntl].y));
                }
        }

        if (kt + 1 < nt) {
            const int nx = cur ^ 1;
            ST_A(nx, ak4, aR0);
            ST_A(nx, ak4 + 16, aR1);
            ST_B(nx, bk, bR0);
            ST_B(nx, bk + 16, bR1);
        }
        __syncthreads();
    }
#undef ST_A
#undef ST_B

    // epilogue: rows g/g+8, cols tg*2, tg*2+1
#pragma unroll
    for (int mt = 0; mt < 2; mt++) {
#pragma unroll
        for (int ntl = 0; ntl < 2; ntl++) {
#pragma unroll
            for (int half = 0; half < 2; half++) {
                const int row = m0 + wm * 32 + mt * 16 + g + half * 8;
                const int col = n0 + wn * 16 + ntl * 8 + tg * 2;
                float v0 = c[mt][ntl][half * 2 + 0];
                float v1 = c[mt][ntl][half * 2 + 1];
                if (bias) { v0 += bias[col]; v1 += bias[col + 1]; }
                if (ACT == 1) {
                    v0 = (v0 > 0.f) ? (v0 + 1.f) : __expf(v0);
                    v1 = (v1 > 0.f) ? (v1 + 1.f) : __expf(v1);
                }
                if (ACT == 2) { v0 = fmaxf(v0, 0.f); v1 = fmaxf(v1, 0.f); }
                float2 o = make_float2(v0, v1);
                *(float2*)&C[(size_t)row * N + col] = o;
            }
        }
    }
}

// Plain GEMM (full K)
template <int ACT>
__global__ __launch_bounds__(256, 2) void gemm_kernel(
    const float* __restrict__ A, const float* __restrict__ B,
    const float* __restrict__ bias, float* __restrict__ C, int N, int K)
{
    gemm_body<ACT>(A, B, bias, C, N, K, 0, K, blockIdx.y * 64, blockIdx.x * 64);
}

// Split-K GEMM
__global__ __launch_bounds__(256, 2) void gemm_splitk_kernel(
    const float* __restrict__ A, const float* __restrict__ B,
    float* __restrict__ Cp, int N, int K, int S)
{
    const int chunk = K / S;
    const int z = blockIdx.z;
    gemm_body<0>(A, B, nullptr, Cp + (size_t)z * NR * N,
                 N, K, z * chunk, (z + 1) * chunk, blockIdx.y * 64, blockIdx.x * 64);
}

// Fused QKV
__global__ __launch_bounds__(256, 2) void gemm_qkv_kernel(
    const float* __restrict__ h,
    const float* __restrict__ Wq, const float* __restrict__ Wk, const float* __restrict__ Wv,
    const float* __restrict__ bq, const float* __restrict__ bk, const float* __restrict__ bv,
    float* __restrict__ q, float* __restrict__ k, float* __restrict__ v, int l)
{
    const size_t w = (size_t)l * DM * DM;
    const int m0 = blockIdx.y * 64, n0 = blockIdx.x * 64;
    if (blockIdx.z == 0)
        gemm_body<1>(h, Wq + w, bq + l * DM, q, DM, DM, 0, DM, m0, n0);
    else if (blockIdx.z == 1)
        gemm_body<1>(h, Wk + w, bk + l * DM, k, DM, DM, 0, DM, m0, n0);
    else
        gemm_body<0>(h, Wv + w, bv + l * DM, v, DM, DM, 0, DM, m0, n0);
}

// ---------------- linear-attention state update + readout ----------------
__global__ void attn_kernel(const float* __restrict__ Q, const float* __restrict__ Kmat,
                            const float* __restrict__ V,
                            const float* __restrict__ Si, const float* __restrict__ Zi,
                            float* __restrict__ S_out, float* __restrict__ Z_out,
                            float* __restrict__ attn)
{
    const int n = blockIdx.x;
    const int h = blockIdx.y;
    const int m = threadIdx.x;

    __shared__ float qs[HE], ks[HE], red[HE];

    const int baseqk = n * DM + h * HE;
    qs[m] = Q[baseqk + m];
    ks[m] = Kmat[baseqk + m];
    const float vm = V[baseqk + m];

    const size_t zbase = ((size_t)n * NH + h) * HE;
    const float z = Zi[zbase + m] + ks[m];
    Z_out[zbase + m] = z;

    red[m] = qs[m] * z;
    __syncthreads();
#pragma unroll
    for (int s = 32; s > 0; s >>= 1) {
        if (m < s) red[m] += red[m + s];
        __syncthreads();
    }
    const float den = red[0] + 1e-6f;

    const size_t sbase = ((size_t)n * NH + h) * HE * HE;
    float num = 0.f;
#pragma unroll 8
    for (int e = 0; e < HE; e++) {
        float s = Si[sbase + (size_t)e * HE + m] + ks[e] * vm;
        S_out[sbase + (size_t)e * HE + m] = s;
        num = fmaf(qs[e], s, num);
    }
    attn[baseqk + m] = num / den;
}

// ---------------- residual + split-K reduce + bias + LayerNorm -----------
__global__ void add_ln_kernel(float* __restrict__ hbuf, const float* __restrict__ part,
                              int P, const float* __restrict__ bias,
                              const float* __restrict__ g, const float* __restrict__ b)
{
    const int n = blockIdx.x;
    const int t = threadIdx.x;
    __shared__ float red[256];
    __shared__ float s_mean, s_rstd;

    float v0 = hbuf[n * DM + t];
    float v1 = hbuf[n * DM + 256 + t];
    for (int p = 0; p < P; p++) {
        v0 += part[(size_t)p * NR * DM + n * DM + t];
        v1 += part[(size_t)p * NR * DM + n * DM + 256 + t];
    }
    if (bias) { v0 += bias[t]; v1 += bias[256 + t]; }

    red[t] = v0 + v1;
    __syncthreads();
#pragma unroll
    for (int s = 128; s > 0; s >>= 1) {
        if (t < s) red[t] += red[t + s];
        __syncthreads();
    }
    if (t == 0) s_mean = red[0] * (1.f / DM);
    __syncthreads();
    const float mean = s_mean;

    float d0 = v0 - mean, d1 = v1 - mean;
    red[t] = d0 * d0 + d1 * d1;
    __syncthreads();
#pragma unroll
    for (int s = 128; s > 0; s >>= 1) {
        if (t < s) red[t] += red[t + s];
        __syncthreads();
    }
    if (t == 0) s_rstd = rsqrtf(red[0] * (1.f / DM) + 1e-5f);
    __syncthreads();
    const float rstd = s_rstd;

    hbuf[n * DM + t]       = d0 * rstd * g[t]       + b[t];
    hbuf[n * DM + 256 + t] = d1 * rstd * g[256 + t] + b[256 + t];
}

// ---------------- host-side launch ----------------
extern "C" void kernel_launch(void* const* d_in, const int* in_sizes, int n_in,
                              void* d_out, int out_size)
{
    const int*   x      = (const int*)  d_in[0];
    const int*   ip     = (const int*)  d_in[1];
    const float* emb    = (const float*)d_in[2];
    const float* pe     = (const float*)d_in[3];
    const float* Wq     = (const float*)d_in[4];
    const float* bq     = (const float*)d_in[5];
    const float* Wk     = (const float*)d_in[6];
    const float* bk     = (const float*)d_in[7];
    const float* Wv     = (const float*)d_in[8];
    const float* bv     = (const float*)d_in[9];
    const float* Wo     = (const float*)d_in[10];
    const float* bo     = (const float*)d_in[11];
    const float* ln1_g  = (const float*)d_in[12];
    const float* ln1_b  = (const float*)d_in[13];
    const float* lin1_w = (const float*)d_in[14];
    const float* lin1_b = (const float*)d_in[15];
    const float* lin2_w = (const float*)d_in[16];
    const float* lin2_b = (const float*)d_in[17];
    const float* ln2_g  = (const float*)d_in[18];
    const float* ln2_b  = (const float*)d_in[19];
    const float* lnf_g  = (const float*)d_in[20];
    const float* lnf_b  = (const float*)d_in[21];
    const float* pred_w = (const float*)d_in[22];
    const float* pred_b = (const float*)d_in[23];
    const float* Si     = (const float*)d_in[24];
    const float* Zi     = (const float*)d_in[25];

    float* out = (float*)d_out;
    float* out_yhat = out;
    float* out_S    = out + (size_t)NR * MIX3;
    float* out_Z    = out_S + (size_t)NL * NR * NH * HE * HE;

    float *h, *q, *k, *v, *attn, *ffn, *part;
    cudaGetSymbolAddress((void**)&h,    g_h);
    cudaGetSymbolAddress((void**)&q,    g_q);
    cudaGetSymbolAddress((void**)&k,    g_k);
    cudaGetSymbolAddress((void**)&v,    g_v);
    cudaGetSymbolAddress((void**)&attn, g_attn);
    cudaGetSymbolAddress((void**)&ffn,  g_ffn);
    cudaGetSymbolAddress((void**)&part, g_part);

    embed_kernel<<<NR, 256>>>(x, ip, emb, pe);

    const dim3 gQKV(DM / 64, NR / 64, 3);
    const dim3 gWo(DM / 64, NR / 64, 2);
    const dim3 gF1(FF / 64, NR / 64);
    const dim3 gF2(DM / 64, NR / 64, 4);
    const dim3 gPred(MIX3 / 64, NR / 64);
    const dim3 gAttn(NR, NH);

    const size_t ssz = (size_t)NR * NH * HE * HE;
    const size_t zsz = (size_t)NR * NH * HE;

    for (int l = 0; l < NL; l++) {
        gemm_qkv_kernel<<<gQKV, 256>>>(h, Wq, Wk, Wv, bq, bk, bv, q, k, v, l);

        attn_kernel<<<gAttn, HE>>>(q, k, v, Si + l * ssz, Zi + l * zsz,
                                   out_S + l * ssz, out_Z + l * zsz, attn);

        gemm_splitk_kernel<<<gWo, 256>>>(attn, Wo + (size_t)l * DM * DM, part, DM, DM, 2);
        add_ln_kernel<<<NR, 256>>>(h, part, 2, bo + l * DM, ln1_g + l * DM, ln1_b + l * DM);

        gemm_kernel<2><<<gF1, 256>>>(h, lin1_w + (size_t)l * DM * FF, lin1_b + l * FF,
                                     ffn, FF, DM);
        gemm_splitk_kernel<<<gF2, 256>>>(ffn, lin2_w + (size_t)l * FF * DM, part, DM, FF, 4);
        add_ln_kernel<<<NR, 256>>>(h, part, 4, lin2_b + l * DM, ln2_g + l * DM, ln2_b + l * DM);
    }

    add_ln_kernel<<<NR, 256>>>(h, (const float*)nullptr, 0, (const float*)nullptr, lnf_g, lnf_b);
    gemm_kernel<0><<<gPred, 256>>>(h, pred_w, pred_b, out_yhat, MIX3, DM);
}